// round 7
// baseline (speedup 1.0000x reference)
#include <cuda_runtime.h>

#define NB 64
#define NT 2048
#define ND 512
#define NU 10
#define CHUNKS 16
#define CROWS (NT / CHUNKS)               // 128 rows per chunk
#define A_WARPS 8
#define A_THREADS 256
#define TB 4
#define NITER (CROWS / (A_WARPS * TB))    // 4
#define WPARTS 4

// Scratch (device globals; no runtime allocation)
__device__ float g_scores[NB * NT];            // raw pre-softmax scores (512 KB)
__device__ float g_pm[NB * CHUNKS];
__device__ float g_pl[NB * CHUNKS];
__device__ float g_pacc[NB * CHUNKS * ND];     // 2 MB

// ---------------- packed f32x2 helpers ----------------
__device__ __forceinline__ unsigned long long pack_dup(float x) {
    unsigned long long r;
    asm("mov.b64 %0, {%1, %1};" : "=l"(r) : "f"(x));
    return r;
}
__device__ __forceinline__ unsigned long long fma2(unsigned long long a,
                                                   unsigned long long b,
                                                   unsigned long long c) {
    unsigned long long d;
    asm("fma.rn.f32x2 %0, %1, %2, %3;" : "=l"(d) : "l"(a), "l"(b), "l"(c));
    return d;
}
__device__ __forceinline__ unsigned long long add2(unsigned long long a,
                                                   unsigned long long b) {
    unsigned long long d;
    asm("add.rn.f32x2 %0, %1, %2;" : "=l"(d) : "l"(a), "l"(b));
    return d;
}
__device__ __forceinline__ void unpack2(unsigned long long p, float& lo, float& hi) {
    asm("mov.b64 {%0, %1}, %2;" : "=f"(lo), "=f"(hi) : "l"(p));
}

// ============ Kernel A: fused score + online-softmax + context partials ============
// Grid: NB*CHUNKS CTAs. CTA = (b, chunk of 128 rows). Warp owns 16 rows, TB=4/iter.
__global__ __launch_bounds__(A_THREADS, 1)
void ka_fused(const float* __restrict__ Eo, const float* __restrict__ H,
              const float* __restrict__ W_eo, const float* __restrict__ b_eo,
              const float* __restrict__ W_h, const float* __restrict__ b_h,
              const float* __restrict__ W_s, const float* __restrict__ b_s,
              float* __restrict__ scores, float* __restrict__ pm,
              float* __restrict__ pl, float* __restrict__ pacc) {
    __shared__ float4 wpk[2][5][4][32];        // 20 KB W_eo packed (f32x2 pairs over u)
    __shared__ float4 macc4[A_WARPS][ND / 4];  // 16 KB warp context partials
    __shared__ float ht[NU];                   // H-term + b_h + b_eo
    __shared__ float w2[NU];                   // -2 * W_s[u]
    __shared__ float sbase;                    // b_s + sum_u W_s[u]
    __shared__ float wm[A_WARPS], wl[A_WARPS];

    int tid = threadIdx.x;
    int warp = tid >> 5, lane = tid & 31;
    int b = blockIdx.x / CHUNKS;
    int c = blockIdx.x % CHUNKS;

    // --- pack W_eo into smem: wpk[h][up][g][lane] covers d=g*128+4*lane+2h(+0,+1), u=2up(+1) ---
    for (int idx = tid; idx < 2 * 5 * 4 * 32; idx += A_THREADS) {
        int h = idx / 640;
        int rem = idx % 640;
        int up = rem / 128;
        int rem2 = rem % 128;
        int g = rem2 / 32;
        int l = rem2 % 32;
        int d0 = g * 128 + l * 4 + h * 2;
        float4 v;
        v.x = W_eo[d0 * NU + 2 * up];
        v.y = W_eo[d0 * NU + 2 * up + 1];
        v.z = W_eo[(d0 + 1) * NU + 2 * up];
        v.w = W_eo[(d0 + 1) * NU + 2 * up + 1];
        wpk[h][up][g][l] = v;
    }

    // --- ht[u] = H[b].W_h[:,u] + b_h[u] + b_eo[u];  w2[u] = -2*W_s[u] ---
    for (int u = warp; u < NU; u += A_WARPS) {
        float p = 0.f;
        for (int d = lane; d < ND; d += 32)
            p += H[b * ND + d] * W_h[d * NU + u];
#pragma unroll
        for (int off = 16; off; off >>= 1)
            p += __shfl_xor_sync(0xffffffffu, p, off);
        if (lane == 0) ht[u] = p + b_h[u] + b_eo[u];
    }
    if (tid < NU) w2[tid] = -2.f * W_s[tid];
    if (tid == 0) {
        float acc = b_s[0];
#pragma unroll
        for (int u = 0; u < NU; u++) acc += W_s[u];
        sbase = acc;                            // tanh(x) = 1 - 2/(e^2x+1)
    }
    __syncthreads();

    float m = -1e30f, l = 0.f;
    float4 ca[4];
#pragma unroll
    for (int g = 0; g < 4; g++) ca[g] = make_float4(0.f, 0.f, 0.f, 0.f);

    long rowbase = (long)b * NT + (long)c * CROWS;

    for (int k = 0; k < NITER; k++) {
        long r0 = rowbase + k * (A_WARPS * TB) + warp * TB;

        // ---- load TB=4 rows (16 LDG.128, batched for MLP) ----
        float4 e[TB][4];
#pragma unroll
        for (int i = 0; i < TB; i++) {
            const float* ep = Eo + (r0 + i) * ND + lane * 4;
#pragma unroll
            for (int g = 0; g < 4; g++)
                e[i][g] = *reinterpret_cast<const float4*>(ep + g * 128);
        }

        // ---- 10 dots per row; W_eo smem loads amortized over TB rows ----
        unsigned long long accs[TB][5];
#pragma unroll
        for (int i = 0; i < TB; i++)
#pragma unroll
            for (int up = 0; up < 5; up++) accs[i][up] = 0ULL;

#pragma unroll
        for (int g = 0; g < 4; g++) {
            unsigned long long d0[TB], d1[TB], d2[TB], d3[TB];
#pragma unroll
            for (int i = 0; i < TB; i++) {
                d0[i] = pack_dup(e[i][g].x);
                d1[i] = pack_dup(e[i][g].y);
                d2[i] = pack_dup(e[i][g].z);
                d3[i] = pack_dup(e[i][g].w);
            }
#pragma unroll
            for (int up = 0; up < 5; up++) {
                ulonglong2 wa = *reinterpret_cast<const ulonglong2*>(&wpk[0][up][g][lane]);
                ulonglong2 wb = *reinterpret_cast<const ulonglong2*>(&wpk[1][up][g][lane]);
#pragma unroll
                for (int i = 0; i < TB; i++) {
                    accs[i][up] = fma2(d0[i], wa.x, accs[i][up]);
                    accs[i][up] = fma2(d1[i], wa.y, accs[i][up]);
                    accs[i][up] = fma2(d2[i], wb.x, accs[i][up]);
                    accs[i][up] = fma2(d3[i], wb.y, accs[i][up]);
                }
            }
        }

        // ---- per-row: butterfly-reduce packs, score, online-softmax update ----
#pragma unroll
        for (int i = 0; i < TB; i++) {
#pragma unroll
            for (int off = 16; off; off >>= 1)
#pragma unroll
                for (int up = 0; up < 5; up++)
                    accs[i][up] = add2(accs[i][up],
                                       __shfl_xor_sync(0xffffffffu, accs[i][up], off));

            // s = sbase + sum_u w2[u]/(exp(2x)+1)   (== b_s + sum W_s*tanh(x))
            float s = sbase;
#pragma unroll
            for (int up = 0; up < 5; up++) {
                float lo, hi;
                unpack2(accs[i][up], lo, hi);
                float x0 = lo + ht[2 * up];
                float x1 = hi + ht[2 * up + 1];
                float e0 = __expf(2.f * x0);
                float e1 = __expf(2.f * x1);
                s += w2[2 * up] * __frcp_rn(e0 + 1.f);
                s += w2[2 * up + 1] * __frcp_rn(e1 + 1.f);
            }

            if (lane == 0) scores[r0 + i] = s;

            if (s > m) {                      // warp-uniform branch
                float sc = __expf(m - s);     // first iter: exp(-huge)=0
                l = l * sc + 1.f;
#pragma unroll
                for (int g = 0; g < 4; g++) {
                    ca[g].x = ca[g].x * sc + e[i][g].x;
                    ca[g].y = ca[g].y * sc + e[i][g].y;
                    ca[g].z = ca[g].z * sc + e[i][g].z;
                    ca[g].w = ca[g].w * sc + e[i][g].w;
                }
                m = s;
            } else {
                float w = __expf(s - m);
                l += w;
#pragma unroll
                for (int g = 0; g < 4; g++) {
                    ca[g].x += w * e[i][g].x;
                    ca[g].y += w * e[i][g].y;
                    ca[g].z += w * e[i][g].z;
                    ca[g].w += w * e[i][g].w;
                }
            }
        }
    }

    // --- merge 8 warps within CTA ---
    if (lane == 0) { wm[warp] = m; wl[warp] = l; }
#pragma unroll
    for (int g = 0; g < 4; g++)
        macc4[warp][g * 32 + lane] = ca[g];
    __syncthreads();

    float mc = wm[0];
#pragma unroll
    for (int w = 1; w < A_WARPS; w++) mc = fmaxf(mc, wm[w]);
    float lc = 0.f;
#pragma unroll
    for (int w = 0; w < A_WARPS; w++) lc += wl[w] * __expf(wm[w] - mc);

    const float* maccf = reinterpret_cast<const float*>(macc4);
    for (int d = tid; d < ND; d += A_THREADS) {
        float v = 0.f;
#pragma unroll
        for (int w = 0; w < A_WARPS; w++)
            v += maccf[w * ND + d] * __expf(wm[w] - mc);
        pacc[(long)(b * CHUNKS + c) * ND + d] = v;
    }
    if (tid == 0) {
        pm[b * CHUNKS + c] = mc;
        pl[b * CHUNKS + c] = lc;
    }
}

// ============ Kernel B: merge chunks -> context + final weights ============
// Grid NB*WPARTS; every CTA recomputes (m, invl); part 0 also writes ctx.
__global__ __launch_bounds__(256)
void kb_merge(const float* __restrict__ scores, const float* __restrict__ pm,
              const float* __restrict__ pl, const float* __restrict__ pacc,
              float* __restrict__ ctx, float* __restrict__ weight) {
    int b = blockIdx.x / WPARTS;
    int part = blockIdx.x % WPARTS;
    int tid = threadIdx.x;
    __shared__ float f[CHUNKS];
    __shared__ float s_m, s_invl;

    if (tid == 0) {
        float m = pm[b * CHUNKS];
#pragma unroll
        for (int c = 1; c < CHUNKS; c++) m = fmaxf(m, pm[b * CHUNKS + c]);
        float l = 0.f;
#pragma unroll
        for (int c = 0; c < CHUNKS; c++)
            l += pl[b * CHUNKS + c] * __expf(pm[b * CHUNKS + c] - m);
        s_m = m;
        s_invl = __fdividef(1.f, l);
    }
    __syncthreads();
    float m = s_m, invl = s_invl;
    if (tid < CHUNKS) f[tid] = __expf(pm[b * CHUNKS + tid] - m) * invl;
    __syncthreads();

    if (part == 0) {
        for (int d = tid; d < ND; d += 256) {
            float v = 0.f;
#pragma unroll
            for (int c = 0; c < CHUNKS; c++)
                v += pacc[(long)(b * CHUNKS + c) * ND + d] * f[c];
            ctx[(long)b * ND + d] = v;
        }
    }

    int tpp = NT / WPARTS;   // 512
    for (int t = part * tpp + tid; t < (part + 1) * tpp; t += 256)
        weight[(long)b * NT + t] = __expf(scores[(long)b * NT + t] - m) * invl;
}

// ================= launch =================
extern "C" void kernel_launch(void* const* d_in, const int* in_sizes, int n_in,
                              void* d_out, int out_size) {
    const float* Eo   = (const float*)d_in[0];
    const float* H    = (const float*)d_in[1];
    const float* W_eo = (const float*)d_in[2];
    const float* b_eo = (const float*)d_in[3];
    const float* W_h  = (const float*)d_in[4];
    const float* b_h  = (const float*)d_in[5];
    const float* W_s  = (const float*)d_in[6];
    const float* b_s  = (const float*)d_in[7];

    float* out    = (float*)d_out;
    float* ctx    = out;            // [B, D]
    float* weight = out + NB * ND;  // [B, T]

    float* scores; cudaGetSymbolAddress((void**)&scores, g_scores);
    float* pm;     cudaGetSymbolAddress((void**)&pm, g_pm);
    float* pl;     cudaGetSymbolAddress((void**)&pl, g_pl);
    float* pacc;   cudaGetSymbolAddress((void**)&pacc, g_pacc);

    ka_fused<<<NB * CHUNKS, A_THREADS>>>(Eo, H, W_eo, b_eo, W_h, b_h, W_s, b_s,
                                         scores, pm, pl, pacc);
    kb_merge<<<NB * WPARTS, 256>>>(scores, pm, pl, pacc, ctx, weight);
}

// round 8
// speedup vs baseline: 1.2213x; 1.2213x over previous
#include <cuda_runtime.h>

#define NB 64
#define NT 2048
#define ND 512
#define NU 10
#define CHUNKS 16
#define CROWS (NT / CHUNKS)               // 128 rows per chunk
#define A_WARPS 8
#define A_THREADS 256
#define TB 2
#define NITER (CROWS / (A_WARPS * TB))    // 8
#define WPARTS 4

// Scratch (device globals; no runtime allocation)
__device__ float g_scores[NB * NT];            // raw pre-softmax scores (512 KB)
__device__ float g_pm[NB * CHUNKS];
__device__ float g_pl[NB * CHUNKS];
__device__ float g_pacc[NB * CHUNKS * ND];     // 2 MB

// ---------------- packed f32x2 helpers ----------------
__device__ __forceinline__ unsigned long long pack_dup(float x) {
    unsigned long long r;
    asm("mov.b64 %0, {%1, %1};" : "=l"(r) : "f"(x));
    return r;
}
__device__ __forceinline__ unsigned long long fma2(unsigned long long a,
                                                   unsigned long long b,
                                                   unsigned long long c) {
    unsigned long long d;
    asm("fma.rn.f32x2 %0, %1, %2, %3;" : "=l"(d) : "l"(a), "l"(b), "l"(c));
    return d;
}
__device__ __forceinline__ unsigned long long add2(unsigned long long a,
                                                   unsigned long long b) {
    unsigned long long d;
    asm("add.rn.f32x2 %0, %1, %2;" : "=l"(d) : "l"(a), "l"(b));
    return d;
}
__device__ __forceinline__ void unpack2(unsigned long long p, float& lo, float& hi) {
    asm("mov.b64 {%0, %1}, %2;" : "=f"(lo), "=f"(hi) : "l"(p));
}

// Dummy kernel: pads the graph to 4 launches so ncu's "-s 5 -c 1" capture
// (flat launch index 5) lands on the 2nd replay's ka_fused instead of kb_merge.
__global__ void kdummy() {}

// ============ Kernel A: fused score + online-softmax + context partials ============
// Grid: NB*CHUNKS CTAs. CTA = (b, chunk of 128 rows). Warp owns 16 rows, TB=2/iter.
// 2 CTAs/SM (16 warps/SM) — R4/R7 A/B showed warp count, not inst count, governs.
__global__ __launch_bounds__(A_THREADS, 2)
void ka_fused(const float* __restrict__ Eo, const float* __restrict__ H,
              const float* __restrict__ W_eo, const float* __restrict__ b_eo,
              const float* __restrict__ W_h, const float* __restrict__ b_h,
              const float* __restrict__ W_s, const float* __restrict__ b_s,
              float* __restrict__ scores, float* __restrict__ pm,
              float* __restrict__ pl, float* __restrict__ pacc) {
    __shared__ float4 wpk[2][5][4][32];        // 20 KB W_eo packed (f32x2 pairs over u)
    __shared__ float4 macc4[A_WARPS][ND / 4];  // 16 KB warp context partials
    __shared__ float ht[NU];                   // H-term + b_h + b_eo
    __shared__ float w2[NU];                   // -2 * W_s[u]
    __shared__ float sbase;                    // b_s + sum_u W_s[u]
    __shared__ float wm[A_WARPS], wl[A_WARPS];

    int tid = threadIdx.x;
    int warp = tid >> 5, lane = tid & 31;
    int b = blockIdx.x / CHUNKS;
    int c = blockIdx.x % CHUNKS;

    // --- pack W_eo into smem: wpk[h][up][g][lane] covers d=g*128+4*lane+2h(+0,+1), u=2up(+1) ---
    for (int idx = tid; idx < 2 * 5 * 4 * 32; idx += A_THREADS) {
        int h = idx / 640;
        int rem = idx % 640;
        int up = rem / 128;
        int rem2 = rem % 128;
        int g = rem2 / 32;
        int l = rem2 % 32;
        int d0 = g * 128 + l * 4 + h * 2;
        float4 v;
        v.x = W_eo[d0 * NU + 2 * up];
        v.y = W_eo[d0 * NU + 2 * up + 1];
        v.z = W_eo[(d0 + 1) * NU + 2 * up];
        v.w = W_eo[(d0 + 1) * NU + 2 * up + 1];
        wpk[h][up][g][l] = v;
    }

    // --- ht[u] = H[b].W_h[:,u] + b_h[u] + b_eo[u];  w2[u] = -2*W_s[u] ---
    for (int u = warp; u < NU; u += A_WARPS) {
        float p = 0.f;
        for (int d = lane; d < ND; d += 32)
            p += H[b * ND + d] * W_h[d * NU + u];
#pragma unroll
        for (int off = 16; off; off >>= 1)
            p += __shfl_xor_sync(0xffffffffu, p, off);
        if (lane == 0) ht[u] = p + b_h[u] + b_eo[u];
    }
    if (tid < NU) w2[tid] = -2.f * W_s[tid];
    if (tid == 0) {
        float acc = b_s[0];
#pragma unroll
        for (int u = 0; u < NU; u++) acc += W_s[u];
        sbase = acc;                            // tanh(x) = 1 - 2/(e^2x+1)
    }
    __syncthreads();

    float m = -1e30f, l = 0.f;
    float4 ca[4];
#pragma unroll
    for (int g = 0; g < 4; g++) ca[g] = make_float4(0.f, 0.f, 0.f, 0.f);

    long rowbase = (long)b * NT + (long)c * CROWS;

    for (int k = 0; k < NITER; k++) {
        long r0 = rowbase + k * (A_WARPS * TB) + warp * TB;

        // ---- load TB=2 rows (8 LDG.128 batched) ----
        float4 e[TB][4];
#pragma unroll
        for (int i = 0; i < TB; i++) {
            const float* ep = Eo + (r0 + i) * ND + lane * 4;
#pragma unroll
            for (int g = 0; g < 4; g++)
                e[i][g] = *reinterpret_cast<const float4*>(ep + g * 128);
        }

        // ---- 10 dots per row; W_eo smem loads amortized over TB rows ----
        unsigned long long accs[TB][5];
#pragma unroll
        for (int i = 0; i < TB; i++)
#pragma unroll
            for (int up = 0; up < 5; up++) accs[i][up] = 0ULL;

#pragma unroll
        for (int g = 0; g < 4; g++) {
            unsigned long long d0[TB], d1[TB], d2[TB], d3[TB];
#pragma unroll
            for (int i = 0; i < TB; i++) {
                d0[i] = pack_dup(e[i][g].x);
                d1[i] = pack_dup(e[i][g].y);
                d2[i] = pack_dup(e[i][g].z);
                d3[i] = pack_dup(e[i][g].w);
            }
#pragma unroll
            for (int up = 0; up < 5; up++) {
                ulonglong2 wa = *reinterpret_cast<const ulonglong2*>(&wpk[0][up][g][lane]);
                ulonglong2 wb = *reinterpret_cast<const ulonglong2*>(&wpk[1][up][g][lane]);
#pragma unroll
                for (int i = 0; i < TB; i++) {
                    accs[i][up] = fma2(d0[i], wa.x, accs[i][up]);
                    accs[i][up] = fma2(d1[i], wa.y, accs[i][up]);
                    accs[i][up] = fma2(d2[i], wb.x, accs[i][up]);
                    accs[i][up] = fma2(d3[i], wb.y, accs[i][up]);
                }
            }
        }

        // ---- per-row: butterfly-reduce packs, score, online-softmax update ----
#pragma unroll
        for (int i = 0; i < TB; i++) {
#pragma unroll
            for (int off = 16; off; off >>= 1)
#pragma unroll
                for (int up = 0; up < 5; up++)
                    accs[i][up] = add2(accs[i][up],
                                       __shfl_xor_sync(0xffffffffu, accs[i][up], off));

            // s = sbase + sum_u w2[u]/(exp(2x)+1)   (== b_s + sum W_s*tanh(x))
            float s = sbase;
#pragma unroll
            for (int up = 0; up < 5; up++) {
                float lo, hi;
                unpack2(accs[i][up], lo, hi);
                float x0 = lo + ht[2 * up];
                float x1 = hi + ht[2 * up + 1];
                float e0 = __expf(2.f * x0);
                float e1 = __expf(2.f * x1);
                s += w2[2 * up] * __frcp_rn(e0 + 1.f);
                s += w2[2 * up + 1] * __frcp_rn(e1 + 1.f);
            }

            if (lane == 0) scores[r0 + i] = s;

            if (s > m) {                      // warp-uniform branch
                float sc = __expf(m - s);     // first iter: exp(-huge)=0
                l = l * sc + 1.f;
#pragma unroll
                for (int g = 0; g < 4; g++) {
                    ca[g].x = ca[g].x * sc + e[i][g].x;
                    ca[g].y = ca[g].y * sc + e[i][g].y;
                    ca[g].z = ca[g].z * sc + e[i][g].z;
                    ca[g].w = ca[g].w * sc + e[i][g].w;
                }
                m = s;
            } else {
                float w = __expf(s - m);
                l += w;
#pragma unroll
                for (int g = 0; g < 4; g++) {
                    ca[g].x += w * e[i][g].x;
                    ca[g].y += w * e[i][g].y;
                    ca[g].z += w * e[i][g].z;
                    ca[g].w += w * e[i][g].w;
                }
            }
        }
    }

    // --- merge 8 warps within CTA ---
    if (lane == 0) { wm[warp] = m; wl[warp] = l; }
#pragma unroll
    for (int g = 0; g < 4; g++)
        macc4[warp][g * 32 + lane] = ca[g];
    __syncthreads();

    float mc = wm[0];
#pragma unroll
    for (int w = 1; w < A_WARPS; w++) mc = fmaxf(mc, wm[w]);
    float lc = 0.f;
#pragma unroll
    for (int w = 0; w < A_WARPS; w++) lc += wl[w] * __expf(wm[w] - mc);

    const float* maccf = reinterpret_cast<const float*>(macc4);
    for (int d = tid; d < ND; d += A_THREADS) {
        float v = 0.f;
#pragma unroll
        for (int w = 0; w < A_WARPS; w++)
            v += maccf[w * ND + d] * __expf(wm[w] - mc);
        pacc[(long)(b * CHUNKS + c) * ND + d] = v;
    }
    if (tid == 0) {
        pm[b * CHUNKS + c] = mc;
        pl[b * CHUNKS + c] = lc;
    }
}

// ============ Kernel B: merge chunks -> context + final weights ============
// Grid NB*WPARTS; every CTA recomputes (m, invl); part 0 also writes ctx.
__global__ __launch_bounds__(256)
void kb_merge(const float* __restrict__ scores, const float* __restrict__ pm,
              const float* __restrict__ pl, const float* __restrict__ pacc,
              float* __restrict__ ctx, float* __restrict__ weight) {
    int b = blockIdx.x / WPARTS;
    int part = blockIdx.x % WPARTS;
    int tid = threadIdx.x;
    __shared__ float f[CHUNKS];
    __shared__ float s_m, s_invl;

    if (tid == 0) {
        float m = pm[b * CHUNKS];
#pragma unroll
        for (int c = 1; c < CHUNKS; c++) m = fmaxf(m, pm[b * CHUNKS + c]);
        float l = 0.f;
#pragma unroll
        for (int c = 0; c < CHUNKS; c++)
            l += pl[b * CHUNKS + c] * __expf(pm[b * CHUNKS + c] - m);
        s_m = m;
        s_invl = __fdividef(1.f, l);
    }
    __syncthreads();
    float m = s_m, invl = s_invl;
    if (tid < CHUNKS) f[tid] = __expf(pm[b * CHUNKS + tid] - m) * invl;
    __syncthreads();

    if (part == 0) {
        for (int d = tid; d < ND; d += 256) {
            float v = 0.f;
#pragma unroll
            for (int c = 0; c < CHUNKS; c++)
                v += pacc[(long)(b * CHUNKS + c) * ND + d] * f[c];
            ctx[(long)b * ND + d] = v;
        }
    }

    int tpp = NT / WPARTS;   // 512
    for (int t = part * tpp + tid; t < (part + 1) * tpp; t += 256)
        weight[(long)b * NT + t] = __expf(scores[(long)b * NT + t] - m) * invl;
}

// ================= launch =================
extern "C" void kernel_launch(void* const* d_in, const int* in_sizes, int n_in,
                              void* d_out, int out_size) {
    const float* Eo   = (const float*)d_in[0];
    const float* H    = (const float*)d_in[1];
    const float* W_eo = (const float*)d_in[2];
    const float* b_eo = (const float*)d_in[3];
    const float* W_h  = (const float*)d_in[4];
    const float* b_h  = (const float*)d_in[5];
    const float* W_s  = (const float*)d_in[6];
    const float* b_s  = (const float*)d_in[7];

    float* out    = (float*)d_out;
    float* ctx    = out;            // [B, D]
    float* weight = out + NB * ND;  // [B, T]

    float* scores; cudaGetSymbolAddress((void**)&scores, g_scores);
    float* pm;     cudaGetSymbolAddress((void**)&pm, g_pm);
    float* pl;     cudaGetSymbolAddress((void**)&pl, g_pl);
    float* pacc;   cudaGetSymbolAddress((void**)&pacc, g_pacc);

    kdummy<<<1, 32>>>();   // pads launch sequence: ncu "-s 5" lands on ka_fused
    ka_fused<<<NB * CHUNKS, A_THREADS>>>(Eo, H, W_eo, b_eo, W_h, b_h, W_s, b_s,
                                         scores, pm, pl, pacc);
    kb_merge<<<NB * WPARTS, 256>>>(scores, pm, pl, pacc, ctx, weight);
    kdummy<<<1, 32>>>();
}